// round 1
// baseline (speedup 1.0000x reference)
#include <cuda_runtime.h>
#include <cuda_bf16.h>
#include <cstdint>

#define ENT_NUM 100000
#define REL_NUM 500
#define DIM     128
#define BATCH   16384
#define ALPHA   0.001f
#define RPAD    129   // padded row stride for conflict-free transposed SMEM reads

// ---- device scratch (no allocations allowed) ----
__device__ int   g_counts[REL_NUM];
__device__ int   g_offsets[REL_NUM + 1];
__device__ int   g_fill[REL_NUM];
__device__ int   g_perm[BATCH];
__device__ float g_part_h2[REL_NUM];
__device__ float g_part_t2[REL_NUM];
__device__ float g_part_r2[REL_NUM];

// ---------------------------------------------------------------------------
__global__ void zero_counts_kernel() {
    int i = blockIdx.x * blockDim.x + threadIdx.x;
    if (i < REL_NUM) g_counts[i] = 0;
}

__global__ void hist_kernel(const int* __restrict__ r_idx) {
    int b = blockIdx.x * blockDim.x + threadIdx.x;
    if (b < BATCH) atomicAdd(&g_counts[r_idx[b]], 1);
}

// single block, 512 threads: inclusive Hillis-Steele scan over 500 counts
__global__ void scan_kernel() {
    __shared__ int s[512];
    int tid = threadIdx.x;
    int v = (tid < REL_NUM) ? g_counts[tid] : 0;
    s[tid] = v;
    __syncthreads();
    for (int o = 1; o < 512; o <<= 1) {
        int add = (tid >= o) ? s[tid - o] : 0;
        __syncthreads();
        s[tid] += add;
        __syncthreads();
    }
    if (tid < REL_NUM) {
        g_offsets[tid + 1] = s[tid];
        g_fill[tid]        = s[tid] - v;   // exclusive prefix
    }
    if (tid == 0) g_offsets[0] = 0;
}

__global__ void scatter_kernel(const int* __restrict__ r_idx) {
    int b = blockIdx.x * blockDim.x + threadIdx.x;
    if (b < BATCH) {
        int pos = atomicAdd(&g_fill[r_idx[b]], 1);
        g_perm[pos] = b;
    }
}

// ---------------------------------------------------------------------------
// Main kernel: one CTA per relation. Loads R (128x128 f32) transposed into
// SMEM once, then processes the relation's batch elements 4 at a time
// (2 per half-block of 128 threads). Thread li owns output row i.
// ---------------------------------------------------------------------------
__global__ __launch_bounds__(256) void rescal_main_kernel(
    const int*   __restrict__ h_idx,
    const int*   __restrict__ r_idx,
    const int*   __restrict__ t_idx,
    const float* __restrict__ ent_w,
    const float* __restrict__ rel_w,
    float*       __restrict__ out)   // out[0]=loss (later), out[1+b]=scores
{
    extern __shared__ float sm[];
    float* Rsm  = sm;                       // DIM * RPAD
    float* tbuf = sm + DIM * RPAD;          // 4 * DIM
    float* red  = tbuf + 4 * DIM;           // 32 (8 warps x 4 values)
    float* misc = red + 32;                 // [0]=relnorm, [1..4]=half accums

    const int r    = blockIdx.x;
    const int tid  = threadIdx.x;
    const int half = tid >> 7;              // 0 or 1
    const int li   = tid & 127;             // row index within half
    const int warp = tid >> 5;
    const int lane = tid & 31;

    // ---- load R transposed (Rsm[j*RPAD+i] = R[i][j]) + Frobenius norm ----
    const float* Rg = rel_w + (size_t)r * (DIM * DIM);
    float ss = 0.f;
    #pragma unroll
    for (int k = 0; k < (DIM * DIM) / 256; k++) {
        int idx = tid + k * 256;
        float v = Rg[idx];
        ss += v * v;
        int i = idx >> 7, j = idx & 127;
        Rsm[j * RPAD + i] = v;
    }
    #pragma unroll
    for (int o = 16; o; o >>= 1) ss += __shfl_xor_sync(0xffffffffu, ss, o);
    if (lane == 0) red[warp] = ss;
    __syncthreads();
    if (tid == 0) {
        float s = 0.f;
        #pragma unroll
        for (int w = 0; w < 8; w++) s += red[w];
        misc[0] = s;
    }
    __syncthreads();   // Rsm + misc[0] ready; red free for reuse

    const int start = g_offsets[r];
    const int n     = g_offsets[r + 1] - start;

    float h2acc = 0.f, t2acc = 0.f;   // live in threads with li==0

    for (int base = 0; base < n; base += 4) {
        int s0i = base + half * 2;
        int s1i = s0i + 1;
        int b0 = (s0i < n) ? g_perm[start + s0i] : -1;
        int b1 = (s1i < n) ? g_perm[start + s1i] : -1;

        float t0 = (b0 >= 0) ? ent_w[(size_t)t_idx[b0] * DIM + li] : 0.f;
        float t1 = (b1 >= 0) ? ent_w[(size_t)t_idx[b1] * DIM + li] : 0.f;
        tbuf[(half * 2 + 0) * DIM + li] = t0;
        tbuf[(half * 2 + 1) * DIM + li] = t1;
        __syncthreads();

        const float* tb0 = &tbuf[(half * 2) * DIM];
        const float* tb1 = tb0 + DIM;
        float tr0 = 0.f, tr1 = 0.f;
        #pragma unroll 8
        for (int j = 0; j < DIM; j++) {
            float rv = Rsm[j * RPAD + li];
            tr0 = fmaf(rv, tb0[j], tr0);
            tr1 = fmaf(rv, tb1[j], tr1);
        }

        float h0 = (b0 >= 0) ? ent_w[(size_t)h_idx[b0] * DIM + li] : 0.f;
        float h1 = (b1 >= 0) ? ent_w[(size_t)h_idx[b1] * DIM + li] : 0.f;
        float sc0 = h0 * tr0;
        float sc1 = h1 * tr1;
        float hh  = h0 * h0 + h1 * h1;
        float tt  = t0 * t0 + t1 * t1;

        #pragma unroll
        for (int o = 16; o; o >>= 1) {
            sc0 += __shfl_xor_sync(0xffffffffu, sc0, o);
            sc1 += __shfl_xor_sync(0xffffffffu, sc1, o);
            hh  += __shfl_xor_sync(0xffffffffu, hh,  o);
            tt  += __shfl_xor_sync(0xffffffffu, tt,  o);
        }
        __syncthreads();   // prior red readers done; tbuf consumers done
        if (lane == 0) {
            red[warp * 4 + 0] = sc0;
            red[warp * 4 + 1] = sc1;
            red[warp * 4 + 2] = hh;
            red[warp * 4 + 3] = tt;
        }
        __syncthreads();
        if (li == 0) {
            int wb = half * 4;
            float S0 = 0.f, S1 = 0.f, HH = 0.f, TT = 0.f;
            #pragma unroll
            for (int w = 0; w < 4; w++) {
                S0 += red[(wb + w) * 4 + 0];
                S1 += red[(wb + w) * 4 + 1];
                HH += red[(wb + w) * 4 + 2];
                TT += red[(wb + w) * 4 + 3];
            }
            if (b0 >= 0) out[1 + b0] = S0;
            if (b1 >= 0) out[1 + b1] = S1;
            h2acc += HH;
            t2acc += TT;
        }
    }

    __syncthreads();
    if (li == 0) {
        misc[1 + half * 2] = h2acc;
        misc[2 + half * 2] = t2acc;
    }
    __syncthreads();
    if (tid == 0) {
        g_part_h2[r] = misc[1] + misc[3];
        g_part_t2[r] = misc[2] + misc[4];
        g_part_r2[r] = misc[0] * (float)n;
    }
}

// ---------------------------------------------------------------------------
__global__ void finalize_kernel(const float* __restrict__ labels,
                                float* __restrict__ out) {
    __shared__ float sred[16 * 4];
    int tid = threadIdx.x;    // 512 threads
    float sq = 0.f;
    for (int b = tid; b < BATCH; b += 512) {
        float d = out[1 + b] - labels[b];
        sq += d * d;
    }
    float h2 = 0.f, t2 = 0.f, r2 = 0.f;
    for (int r = tid; r < REL_NUM; r += 512) {
        h2 += g_part_h2[r];
        t2 += g_part_t2[r];
        r2 += g_part_r2[r];
    }
    #pragma unroll
    for (int o = 16; o; o >>= 1) {
        sq += __shfl_xor_sync(0xffffffffu, sq, o);
        h2 += __shfl_xor_sync(0xffffffffu, h2, o);
        t2 += __shfl_xor_sync(0xffffffffu, t2, o);
        r2 += __shfl_xor_sync(0xffffffffu, r2, o);
    }
    int warp = tid >> 5, lane = tid & 31;
    if (lane == 0) {
        sred[warp * 4 + 0] = sq;
        sred[warp * 4 + 1] = h2;
        sred[warp * 4 + 2] = t2;
        sred[warp * 4 + 3] = r2;
    }
    __syncthreads();
    if (tid == 0) {
        float SQ = 0.f, H2 = 0.f, T2 = 0.f, R2 = 0.f;
        #pragma unroll
        for (int w = 0; w < 16; w++) {
            SQ += sred[w * 4 + 0];
            H2 += sred[w * 4 + 1];
            T2 += sred[w * 4 + 2];
            R2 += sred[w * 4 + 3];
        }
        float mh = H2 / ((float)BATCH * DIM);
        float mt = T2 / ((float)BATCH * DIM);
        float mr = R2 / ((float)BATCH * DIM * DIM);
        float norms = (mh + mt + mr) / 3.0f;
        out[0] = SQ / (float)BATCH + ALPHA * norms;
    }
}

// ---------------------------------------------------------------------------
extern "C" void kernel_launch(void* const* d_in, const int* in_sizes, int n_in,
                              void* d_out, int out_size) {
    const int*   h_idx  = (const int*)  d_in[0];
    const int*   r_idx  = (const int*)  d_in[1];
    const int*   t_idx  = (const int*)  d_in[2];
    const float* labels = (const float*)d_in[3];
    const float* ent_w  = (const float*)d_in[4];
    const float* rel_w  = (const float*)d_in[5];
    float* out = (float*)d_out;

    const int smem_main = (DIM * RPAD + 4 * DIM + 32 + 8) * sizeof(float);
    cudaFuncSetAttribute(rescal_main_kernel,
                         cudaFuncAttributeMaxDynamicSharedMemorySize, smem_main);

    zero_counts_kernel<<<1, 512>>>();
    hist_kernel<<<BATCH / 256, 256>>>(r_idx);
    scan_kernel<<<1, 512>>>();
    scatter_kernel<<<BATCH / 256, 256>>>(r_idx);
    rescal_main_kernel<<<REL_NUM, 256, smem_main>>>(h_idx, r_idx, t_idx,
                                                    ent_w, rel_w, out);
    finalize_kernel<<<1, 512>>>(labels, out);
}

// round 2
// speedup vs baseline: 1.3281x; 1.3281x over previous
#include <cuda_runtime.h>
#include <cstdint>

#define ENT_NUM 100000
#define REL_NUM 500
#define DIM     128
#define BATCH   16384
#define ALPHA   0.001f

// ---- device scratch (no allocations allowed) ----
__device__ int   g_offsets[REL_NUM + 1];
__device__ int   g_perm[BATCH];
__device__ float g_part_h2[REL_NUM];
__device__ float g_part_t2[REL_NUM];
__device__ float g_part_r2[REL_NUM];

// ---------------------------------------------------------------------------
// packed f32x2 helpers (sm_100+)
// ---------------------------------------------------------------------------
__device__ __forceinline__ unsigned long long ffma2(unsigned long long a,
                                                    unsigned long long b,
                                                    unsigned long long c) {
    asm("fma.rn.f32x2 %0, %1, %2, %0;" : "+l"(c) : "l"(a), "l"(b));
    return c;
}
__device__ __forceinline__ unsigned long long pk2(float x, float y) {
    unsigned long long r;
    asm("mov.b64 %0, {%1, %2};" : "=l"(r) : "f"(x), "f"(y));
    return r;
}
__device__ __forceinline__ float2 unpk2(unsigned long long v) {
    float2 r;
    asm("mov.b64 {%0, %1}, %2;" : "=f"(r.x), "=f"(r.y) : "l"(v));
    return r;
}

// ---------------------------------------------------------------------------
// ONE-block preprocessing: histogram + scan + scatter (replaces 4 kernels)
// ---------------------------------------------------------------------------
__global__ __launch_bounds__(1024) void preprocess_kernel(
    const int* __restrict__ r_idx)
{
    __shared__ int hist[512];
    __shared__ int scn[512];
    const int tid = threadIdx.x;

    if (tid < 512) hist[tid] = 0;
    __syncthreads();

    int rloc[16];
    #pragma unroll
    for (int k = 0; k < 16; k++) {
        rloc[k] = r_idx[tid + k * 1024];
        atomicAdd(&hist[rloc[k]], 1);
    }
    __syncthreads();

    int v = 0;
    if (tid < 512) { v = hist[tid]; scn[tid] = v; }
    __syncthreads();
    for (int o = 1; o < 512; o <<= 1) {
        int add = 0;
        if (tid < 512 && tid >= o) add = scn[tid - o];
        __syncthreads();
        if (tid < 512) scn[tid] += add;
        __syncthreads();
    }
    if (tid < 512) {
        if (tid < REL_NUM) g_offsets[tid + 1] = scn[tid];
        hist[tid] = scn[tid] - v;            // exclusive prefix -> fill ctr
    }
    if (tid == 0) g_offsets[0] = 0;
    __syncthreads();

    #pragma unroll
    for (int k = 0; k < 16; k++) {
        int pos = atomicAdd(&hist[rloc[k]], 1);
        g_perm[pos] = tid + k * 1024;
    }
}

// ---------------------------------------------------------------------------
// Main kernel: one CTA per relation. Each thread keeps a 64-float half-row
// of R in REGISTERS (as 32 packed f32x2). Processes 4 batch elements per
// iteration with prefetched entity gathers. Crossbar carries only t
// broadcasts (LDS.128).
// ---------------------------------------------------------------------------
__global__ __launch_bounds__(256, 2) void rescal_main_kernel(
    const int*   __restrict__ h_idx,
    const int*   __restrict__ t_idx,
    const float* __restrict__ ent_w,
    const float* __restrict__ rel_w,
    float*       __restrict__ out)     // out[0]=loss, out[1+b]=scores
{
    __shared__ __align__(16) float t_sm[4][DIM];
    __shared__ float h_sm[4][DIM];
    __shared__ float red[4][8];        // [element][warp]
    __shared__ float red2[8][3];       // final hh/tt/ss per warp
    __shared__ int   bs_sm[4];

    const int r    = blockIdx.x;
    const int tid  = threadIdx.x;
    const int li   = tid & 127;        // row index
    const int ch   = tid >> 7;         // column half: 0 -> cols 0..63, 1 -> 64..127
    const int warp = tid >> 5;
    const int lane = tid & 31;

    // ---- load half-row of R into registers + Frobenius partial ----
    const float4* Rg = reinterpret_cast<const float4*>(
        rel_w + (size_t)r * (DIM * DIM) + (size_t)li * DIM + ch * 64);
    unsigned long long Rlo[16], Rhi[16];
    float ss = 0.f;
    #pragma unroll
    for (int k = 0; k < 16; k++) {
        float4 v = Rg[k];
        ss += v.x * v.x + v.y * v.y + v.z * v.z + v.w * v.w;
        Rlo[k] = pk2(v.x, v.y);
        Rhi[k] = pk2(v.z, v.w);
    }

    const int start = g_offsets[r];
    const int n     = g_offsets[r + 1] - start;

    // ---- prefetch iteration 0 (this thread stages elements ch and ch+2) ----
    float pt0 = 0.f, pt1 = 0.f, ph0 = 0.f, ph1 = 0.f;
    int pb0 = (ch < n)     ? g_perm[start + ch]     : -1;
    int pb1 = (ch + 2 < n) ? g_perm[start + ch + 2] : -1;
    if (pb0 >= 0) {
        pt0 = ent_w[(size_t)t_idx[pb0] * DIM + li];
        ph0 = ent_w[(size_t)h_idx[pb0] * DIM + li];
    }
    if (pb1 >= 0) {
        pt1 = ent_w[(size_t)t_idx[pb1] * DIM + li];
        ph1 = ent_w[(size_t)h_idx[pb1] * DIM + li];
    }

    float hh = 0.f, tt = 0.f;

    for (int base = 0; base < n; base += 4) {
        __syncthreads();               // previous iter's smem readers done
        t_sm[ch][li]     = pt0;
        t_sm[ch + 2][li] = pt1;
        h_sm[ch][li]     = ph0;
        h_sm[ch + 2][li] = ph1;
        if (li == 0) { bs_sm[ch] = pb0; bs_sm[ch + 2] = pb1; }
        hh += ph0 * ph0 + ph1 * ph1;
        tt += pt0 * pt0 + pt1 * pt1;

        // prefetch next iteration (latency hides under compute below)
        {
            int nb = base + 4;
            pb0 = (nb + ch < n)     ? g_perm[start + nb + ch]     : -1;
            pb1 = (nb + ch + 2 < n) ? g_perm[start + nb + ch + 2] : -1;
            pt0 = pt1 = ph0 = ph1 = 0.f;
            if (pb0 >= 0) {
                pt0 = ent_w[(size_t)t_idx[pb0] * DIM + li];
                ph0 = ent_w[(size_t)h_idx[pb0] * DIM + li];
            }
            if (pb1 >= 0) {
                pt1 = ent_w[(size_t)t_idx[pb1] * DIM + li];
                ph1 = ent_w[(size_t)h_idx[pb1] * DIM + li];
            }
        }
        __syncthreads();               // staged smem visible

        // ---- 4 matvec partials from register-resident R ----
        unsigned long long alo[4] = {0ull, 0ull, 0ull, 0ull};
        unsigned long long ahi[4] = {0ull, 0ull, 0ull, 0ull};
        #pragma unroll
        for (int k = 0; k < 16; k++) {
            #pragma unroll
            for (int e = 0; e < 4; e++) {
                ulonglong2 tv = *reinterpret_cast<const ulonglong2*>(
                    &t_sm[e][ch * 64 + k * 4]);       // LDS.128 broadcast
                alo[e] = ffma2(Rlo[k], tv.x, alo[e]);
                ahi[e] = ffma2(Rhi[k], tv.y, ahi[e]);
            }
        }

        float sc[4];
        #pragma unroll
        for (int e = 0; e < 4; e++) {
            float2 lo = unpk2(alo[e]);
            float2 hi = unpk2(ahi[e]);
            float p = (lo.x + lo.y) + (hi.x + hi.y);
            sc[e] = h_sm[e][li] * p;
        }

        // reduce 4 scores across 256 threads
        #pragma unroll
        for (int o = 16; o; o >>= 1) {
            #pragma unroll
            for (int e = 0; e < 4; e++)
                sc[e] += __shfl_xor_sync(0xffffffffu, sc[e], o);
        }
        if (lane == 0) {
            #pragma unroll
            for (int e = 0; e < 4; e++) red[e][warp] = sc[e];
        }
        __syncthreads();
        if (tid < 4) {
            float S = 0.f;
            #pragma unroll
            for (int w = 0; w < 8; w++) S += red[tid][w];
            int b = bs_sm[tid];
            if (b >= 0) out[1 + b] = S;
        }
    }

    // ---- final block reductions: hh, tt, ss ----
    __syncthreads();
    #pragma unroll
    for (int o = 16; o; o >>= 1) {
        hh += __shfl_xor_sync(0xffffffffu, hh, o);
        tt += __shfl_xor_sync(0xffffffffu, tt, o);
        ss += __shfl_xor_sync(0xffffffffu, ss, o);
    }
    if (lane == 0) { red2[warp][0] = hh; red2[warp][1] = tt; red2[warp][2] = ss; }
    __syncthreads();
    if (tid == 0) {
        float HH = 0.f, TT = 0.f, SS = 0.f;
        #pragma unroll
        for (int w = 0; w < 8; w++) {
            HH += red2[w][0]; TT += red2[w][1]; SS += red2[w][2];
        }
        g_part_h2[r] = HH;
        g_part_t2[r] = TT;
        g_part_r2[r] = SS * (float)n;
    }
}

// ---------------------------------------------------------------------------
__global__ void finalize_kernel(const float* __restrict__ labels,
                                float* __restrict__ out) {
    __shared__ float sred[16 * 4];
    int tid = threadIdx.x;    // 512 threads
    float sq = 0.f;
    for (int b = tid; b < BATCH; b += 512) {
        float d = out[1 + b] - labels[b];
        sq += d * d;
    }
    float h2 = 0.f, t2 = 0.f, r2 = 0.f;
    for (int r = tid; r < REL_NUM; r += 512) {
        h2 += g_part_h2[r];
        t2 += g_part_t2[r];
        r2 += g_part_r2[r];
    }
    #pragma unroll
    for (int o = 16; o; o >>= 1) {
        sq += __shfl_xor_sync(0xffffffffu, sq, o);
        h2 += __shfl_xor_sync(0xffffffffu, h2, o);
        t2 += __shfl_xor_sync(0xffffffffu, t2, o);
        r2 += __shfl_xor_sync(0xffffffffu, r2, o);
    }
    int warp = tid >> 5, lane = tid & 31;
    if (lane == 0) {
        sred[warp * 4 + 0] = sq;
        sred[warp * 4 + 1] = h2;
        sred[warp * 4 + 2] = t2;
        sred[warp * 4 + 3] = r2;
    }
    __syncthreads();
    if (tid == 0) {
        float SQ = 0.f, H2 = 0.f, T2 = 0.f, R2 = 0.f;
        #pragma unroll
        for (int w = 0; w < 16; w++) {
            SQ += sred[w * 4 + 0];
            H2 += sred[w * 4 + 1];
            T2 += sred[w * 4 + 2];
            R2 += sred[w * 4 + 3];
        }
        float mh = H2 / ((float)BATCH * DIM);
        float mt = T2 / ((float)BATCH * DIM);
        float mr = R2 / ((float)BATCH * DIM * DIM);
        float norms = (mh + mt + mr) / 3.0f;
        out[0] = SQ / (float)BATCH + ALPHA * norms;
    }
}

// ---------------------------------------------------------------------------
extern "C" void kernel_launch(void* const* d_in, const int* in_sizes, int n_in,
                              void* d_out, int out_size) {
    const int*   h_idx  = (const int*)  d_in[0];
    const int*   r_idx  = (const int*)  d_in[1];
    const int*   t_idx  = (const int*)  d_in[2];
    const float* labels = (const float*)d_in[3];
    const float* ent_w  = (const float*)d_in[4];
    const float* rel_w  = (const float*)d_in[5];
    float* out = (float*)d_out;

    preprocess_kernel<<<1, 1024>>>(r_idx);
    rescal_main_kernel<<<REL_NUM, 256>>>(h_idx, t_idx, ent_w, rel_w, out);
    finalize_kernel<<<1, 512>>>(labels, out);
}